// round 9
// baseline (speedup 1.0000x reference)
#include <cuda_runtime.h>
#include <math.h>

// Problem constants (fixed by setup_inputs)
#define C_IN   64
#define C_OUT  128
#define NPAIR  2048            // B*T = 16*128
#define NCP    32              // c-pairs = C_IN/2

#define THREADS 128            // 4 pairs (1 per warp) x 32 o-pairs (2 o per thread)
#define PAIRS_PER_BLOCK 4

__device__ __forceinline__ float fsin_ap(float a) {
    float r; asm("sin.approx.f32 %0, %1;" : "=f"(r) : "f"(a)); return r;
}
__device__ __forceinline__ float frsq_ap(float a) {
    float r; asm("rsqrt.approx.f32 %0, %1;" : "=f"(r) : "f"(a)); return r;
}
__device__ __forceinline__ float frcp_ap(float a) {
    float r; asm("rcp.approx.f32 %0, %1;" : "=f"(r) : "f"(a)); return r;
}

__global__ __launch_bounds__(THREADS, 8)   // force <=64 regs
void qpu_kernel(const float* __restrict__ x,      // (NPAIR, 4*C_IN) [r|i|j|k]
                const float* __restrict__ weight, // (C_OUT, C_IN)
                const float* __restrict__ bias,   // (C_OUT)
                float* __restrict__ out)          // (NPAIR, 4*C_OUT)
{
    // Interleaved pairwise preprocess: pre[pp][cp] = {A, B, C} at imm offsets 0/16/32
    //   A = {th01, v1}   B = {th02, v2}   C = {v1.v2, v1 x v2}
    __shared__ float4 pre[PAIRS_PER_BLOCK][NCP][3];
    // weight quads, power-of-two stride: w4_s[cp*32+oh] = {w(o0,c1),w(o0,c2),w(o1,c1),w(o1,c2)}
    __shared__ float4 w4_s[NCP * 32];

    const int tid   = threadIdx.x;
    const int p0    = blockIdx.x * PAIRS_PER_BLOCK;
    const int obase = blockIdx.y * 64;

    // ---- stage weight quads (coalesced LDG, scalar scatter) ----
    #pragma unroll
    for (int idx = tid; idx < 64 * C_IN; idx += THREADS) {
        int ol = idx >> 6;        // local o 0..63
        int c  = idx & 63;
        float v = weight[(obase + ol) * C_IN + c];
        int cp   = c >> 1;
        int comp = ((ol & 1) << 1) | (c & 1);
        ((float*)&w4_s[(cp << 5) + (ol >> 1)])[comp] = v;
    }

    // ---- per-(pair, c-pair) preprocessing ----
    {
        int pp = tid >> 5;        // 0..3 (one pair per warp)
        int cp = tid & 31;
        const float* xr = x + (size_t)(p0 + pp) * (4 * C_IN);
        int c1 = 2 * cp, c2 = 2 * cp + 1;
        const float CL = 1.0f - 1e-6f;

        float r1 = xr[c1], i1 = xr[C_IN + c1], j1 = xr[2*C_IN + c1], k1 = xr[3*C_IN + c1];
        float r2 = xr[c2], i2 = xr[C_IN + c2], j2 = xr[2*C_IN + c2], k2 = xr[3*C_IN + c2];

        float n1 = rsqrtf(fmaf(i1, i1, fmaf(j1, j1, fmaf(k1, k1, 1e-12f))));
        float n2 = rsqrtf(fmaf(i2, i2, fmaf(j2, j2, fmaf(k2, k2, 1e-12f))));
        float t01 = acosf(fminf(fmaxf(r1, -CL), CL));
        float t02 = acosf(fminf(fmaxf(r2, -CL), CL));

        float ax = i1 * n1, ay = j1 * n1, az = k1 * n1;
        float bx = i2 * n2, by = j2 * n2, bz = k2 * n2;
        float d  = fmaf(ax, bx, fmaf(ay, by, az * bz));
        float cx = fmaf(ay, bz, -az * by);
        float cy = fmaf(az, bx, -ax * bz);
        float cz = fmaf(ax, by, -ay * bx);

        pre[pp][cp][0] = make_float4(t01, ax, ay, az);
        pre[pp][cp][1] = make_float4(t02, bx, by, bz);
        pre[pp][cp][2] = make_float4(d, cx, cy, cz);
    }
    __syncthreads();

    // ---- main loop: one thread = (one pair, two o-chains), c-pairs combined ----
    const int pp = tid >> 5;
    const int oh = tid & 31;
    const float2 b2 = ((const float2*)bias)[blockIdx.y * 32 + oh];
    const float4* preb = &pre[pp][0][0];     // A,B,C at +0,+1,+2; step 3 per cp
    const float4* wb   = &w4_s[oh];          // step 32 per cp

    float ar0, ai0, aj0, ak0, ar1, ai1, aj1, ak1;

    // Pairwise quaternion in tan-normalized form (q_r divided out via MUFU.RCP):
    // coefs u1,u2,u12 scale A.v, B.v, C.v; |th| <= 0.733 -> qr >= 0.19.
    #define QPAIR(WA, WB, BB, QX, QY, QZ)                                       \
        float QX, QY, QZ;                                                       \
        {                                                                       \
            float th1 = fmaf((WA), A.x, (BB));                                  \
            float th2 = fmaf((WB), B.x, (BB));                                  \
            float s1  = fsin_ap(th1);                                           \
            float s2  = fsin_ap(th2);                                           \
            float t1  = s1 * frsq_ap(fmaf(-s1, s1, 1.0f));                      \
            float t2  = s2 * frsq_ap(fmaf(-s2, s2, 1.0f));                      \
            float t12 = t1 * t2;                                                \
            float rc  = frcp_ap(fmaf(-t12, C.x, 1.0f));                         \
            float u1  = t1 * rc;                                                \
            float u2  = t2 * rc;                                                \
            float u12 = t12 * rc;                                               \
            QX = fmaf(u12, C.y, fmaf(u2, B.y, u1 * A.y));                       \
            QY = fmaf(u12, C.z, fmaf(u2, B.z, u1 * A.z));                       \
            QZ = fmaf(u12, C.w, fmaf(u2, B.w, u1 * A.w));                       \
        }

    // peel cp = 0: acc = pair quaternion (tan form: (1, q))
    {
        float4 A = preb[0];
        float4 B = preb[1];
        float4 C = preb[2];
        float4 w = wb[0];
        QPAIR(w.x, w.y, b2.x, qx0, qy0, qz0);
        ar0 = 1.0f; ai0 = qx0; aj0 = qy0; ak0 = qz0;
        QPAIR(w.z, w.w, b2.y, qx1, qy1, qz1);
        ar1 = 1.0f; ai1 = qx1; aj1 = qy1; ak1 = qz1;
    }

    #pragma unroll 4
    for (int cp = 1; cp < NCP; ++cp) {
        float4 A = preb[cp * 3];
        float4 B = preb[cp * 3 + 1];
        float4 C = preb[cp * 3 + 2];
        float4 w = wb[cp << 5];

        // chain 0: acc = acc (x) (1, q)  -- 12 FMA
        {
            QPAIR(w.x, w.y, b2.x, qx, qy, qz);
            float nr = ar0; nr = fmaf(-ai0, qx, nr); nr = fmaf(-aj0, qy, nr); nr = fmaf(-ak0, qz, nr);
            float ni = ai0; ni = fmaf( ar0, qx, ni); ni = fmaf( aj0, qz, ni); ni = fmaf(-ak0, qy, ni);
            float nj = aj0; nj = fmaf( ar0, qy, nj); nj = fmaf(-ai0, qz, nj); nj = fmaf( ak0, qx, nj);
            float nk = ak0; nk = fmaf( ar0, qz, nk); nk = fmaf( ai0, qy, nk); nk = fmaf(-aj0, qx, nk);
            ar0 = nr; ai0 = ni; aj0 = nj; ak0 = nk;
        }
        // chain 1 (independent)
        {
            QPAIR(w.z, w.w, b2.y, qx, qy, qz);
            float nr = ar1; nr = fmaf(-ai1, qx, nr); nr = fmaf(-aj1, qy, nr); nr = fmaf(-ak1, qz, nr);
            float ni = ai1; ni = fmaf( ar1, qx, ni); ni = fmaf( aj1, qz, ni); ni = fmaf(-ak1, qy, ni);
            float nj = aj1; nj = fmaf( ar1, qy, nj); nj = fmaf(-ai1, qz, nj); nj = fmaf( ak1, qx, nj);
            float nk = ak1; nk = fmaf( ar1, qz, nk); nk = fmaf( ai1, qy, nk); nk = fmaf(-aj1, qx, nk);
            ar1 = nr; ai1 = ni; aj1 = nj; ak1 = nk;
        }
    }
    #undef QPAIR

    // ---- normalize + coalesced float2 writes ----
    float rn0 = rsqrtf(fmaf(ar0, ar0, fmaf(ai0, ai0, fmaf(aj0, aj0, fmaf(ak0, ak0, 1e-12f)))));
    float rn1 = rsqrtf(fmaf(ar1, ar1, fmaf(ai1, ai1, fmaf(aj1, aj1, fmaf(ak1, ak1, 1e-12f)))));

    float2* op = (float2*)(out + (size_t)(p0 + pp) * (4 * C_OUT) + obase);
    op[oh]       = make_float2(ar0 * rn0, ar1 * rn1);
    op[64 + oh]  = make_float2(ai0 * rn0, ai1 * rn1);
    op[128 + oh] = make_float2(aj0 * rn0, aj1 * rn1);
    op[192 + oh] = make_float2(ak0 * rn0, ak1 * rn1);
}

extern "C" void kernel_launch(void* const* d_in, const int* in_sizes, int n_in,
                              void* d_out, int out_size) {
    const float* x      = (const float*)d_in[0];
    const float* weight = (const float*)d_in[1];
    const float* bias   = (const float*)d_in[2];
    float* out = (float*)d_out;
    (void)in_sizes; (void)n_in; (void)out_size;

    dim3 grid(NPAIR / PAIRS_PER_BLOCK, 2);   // 512 x 2 = 1024 blocks
    qpu_kernel<<<grid, THREADS>>>(x, weight, bias, out);
}

// round 11
// speedup vs baseline: 1.1635x; 1.1635x over previous
#include <cuda_runtime.h>
#include <math.h>

// Problem constants (fixed by setup_inputs)
#define C_IN   64
#define C_OUT  128
#define NPAIR  2048            // B*T = 16*128

#define THREADS 128            // 4 pairs x 32 o-pairs (2 o per thread)
#define PAIRS_PER_BLOCK 4
#define OH_PER_BLOCK 32        // o-pairs per block -> 64 o per block
#define WS2 33                 // padded float2 stride (conflict-free)

__device__ __forceinline__ float fsin_ap(float a) {
    float r; asm("sin.approx.f32 %0, %1;" : "=f"(r) : "f"(a)); return r;
}
__device__ __forceinline__ float fcos_ap(float a) {
    float r; asm("cos.approx.f32 %0, %1;" : "=f"(r) : "f"(a)); return r;
}
__device__ __forceinline__ float frcp_ap(float a) {
    float r; asm("rcp.approx.f32 %0, %1;" : "=f"(r) : "f"(a)); return r;
}

__global__ __launch_bounds__(THREADS, 8)
void qpu_kernel(const float* __restrict__ x,      // (NPAIR, 4*C_IN) [r|i|j|k]
                const float* __restrict__ weight, // (C_OUT, C_IN)
                const float* __restrict__ bias,   // (C_OUT)
                float* __restrict__ out)          // (NPAIR, 4*C_OUT)
{
    __shared__ float2 w2_s[C_IN * WS2];             // [c*33 + oh] = {w[2oh], w[2oh+1]} transposed
    __shared__ float4 pc[PAIRS_PER_BLOCK][C_IN];    // {theta0, i*rn, j*rn, k*rn}

    const int tid   = threadIdx.x;
    const int p0    = blockIdx.x * PAIRS_PER_BLOCK;
    const int obase = blockIdx.y * (2 * OH_PER_BLOCK);   // 0 or 64

    // ---- stage this block's o-slice of weight, transposed, packed by o-pair ----
    #pragma unroll
    for (int idx = tid; idx < OH_PER_BLOCK * C_IN; idx += THREADS) {
        int ol = idx >> 6;     // local o-pair 0..31
        int c  = idx & 63;
        float wa = weight[(obase + 2 * ol) * C_IN + c];
        float wb = weight[(obase + 2 * ol + 1) * C_IN + c];
        w2_s[c * WS2 + ol] = make_float2(wa, wb);
    }

    // ---- per-(pair,c) preprocessing: theta0 = acos(clip(r)), unit axis ----
    #pragma unroll
    for (int idx = tid; idx < PAIRS_PER_BLOCK * C_IN; idx += THREADS) {
        int pp = idx >> 6;
        int c  = idx & 63;
        const float* xr = x + (size_t)(p0 + pp) * (4 * C_IN);
        float r = xr[c];
        float i = xr[C_IN + c];
        float j = xr[2 * C_IN + c];
        float k = xr[3 * C_IN + c];
        float rn = rsqrtf(fmaf(i, i, fmaf(j, j, fmaf(k, k, 1e-12f))));
        const float CLAMP = 1.0f - 1e-6f;
        float rc = fminf(fmaxf(r, -CLAMP), CLAMP);
        float t0 = acosf(rc);
        pc[pp][c] = make_float4(t0, i * rn, j * rn, k * rn);
    }
    __syncthreads();

    // ---- main loop: one thread = (one pair, two adjacent o) ----
    const int pp = tid >> 5;          // pair within block (0..3)
    const int oh = tid & 31;          // local o-pair
    const float2 b2 = ((const float2*)bias)[(obase >> 1) + oh];

    // tan-normalized accumulators; implicit prod(cos) folds into final normalize
    float ar0 = 1.0f, ai0 = 0.0f, aj0 = 0.0f, ak0 = 0.0f;
    float ar1 = 1.0f, ai1 = 0.0f, aj1 = 0.0f, ak1 = 0.0f;

    #pragma unroll 8
    for (int c = 0; c < C_IN; ++c) {
        float4 p  = pc[pp][c];                 // LDS.128 broadcast
        float2 w2 = w2_s[c * WS2 + oh];        // LDS.64 conflict-free

        // chain 0:  tan = sin * rcp(cos)  (1 FMUL + 3 MUFU; cos >= 0.74)
        float th0 = fmaf(w2.x, p.x, b2.x);     // |th| <= 0.733 < pi/2
        float t0  = fsin_ap(th0) * frcp_ap(fcos_ap(th0));
        float qi0 = p.y * t0, qj0 = p.z * t0, qk0 = p.w * t0;

        float nr0 = ar0; nr0 = fmaf(-ai0, qi0, nr0); nr0 = fmaf(-aj0, qj0, nr0); nr0 = fmaf(-ak0, qk0, nr0);
        float ni0 = ai0; ni0 = fmaf( ar0, qi0, ni0); ni0 = fmaf( aj0, qk0, ni0); ni0 = fmaf(-ak0, qj0, ni0);
        float nj0 = aj0; nj0 = fmaf( ar0, qj0, nj0); nj0 = fmaf(-ai0, qk0, nj0); nj0 = fmaf( ak0, qi0, nj0);
        float nk0 = ak0; nk0 = fmaf( ar0, qk0, nk0); nk0 = fmaf( ai0, qj0, nk0); nk0 = fmaf(-aj0, qi0, nk0);
        ar0 = nr0; ai0 = ni0; aj0 = nj0; ak0 = nk0;

        // chain 1 (independent -> hides MUFU/FMA latency)
        float th1 = fmaf(w2.y, p.x, b2.y);
        float t1  = fsin_ap(th1) * frcp_ap(fcos_ap(th1));
        float qi1 = p.y * t1, qj1 = p.z * t1, qk1 = p.w * t1;

        float nr1 = ar1; nr1 = fmaf(-ai1, qi1, nr1); nr1 = fmaf(-aj1, qj1, nr1); nr1 = fmaf(-ak1, qk1, nr1);
        float ni1 = ai1; ni1 = fmaf( ar1, qi1, ni1); ni1 = fmaf( aj1, qk1, ni1); ni1 = fmaf(-ak1, qj1, ni1);
        float nj1 = aj1; nj1 = fmaf( ar1, qj1, nj1); nj1 = fmaf(-ai1, qk1, nj1); nj1 = fmaf( ak1, qi1, nj1);
        float nk1 = ak1; nk1 = fmaf( ar1, qk1, nk1); nk1 = fmaf( ai1, qj1, nk1); nk1 = fmaf(-aj1, qi1, nk1);
        ar1 = nr1; ai1 = ni1; aj1 = nj1; ak1 = nk1;
    }

    // ---- normalize + coalesced float2 writes ----
    float rn0 = rsqrtf(fmaf(ar0, ar0, fmaf(ai0, ai0, fmaf(aj0, aj0, fmaf(ak0, ak0, 1e-12f)))));
    float rn1 = rsqrtf(fmaf(ar1, ar1, fmaf(ai1, ai1, fmaf(aj1, aj1, fmaf(ak1, ak1, 1e-12f)))));

    float2* op = (float2*)(out + (size_t)(p0 + pp) * (4 * C_OUT) + obase);
    op[oh]                       = make_float2(ar0 * rn0, ar1 * rn1);
    op[(C_OUT >> 1) * 1 + oh]    = make_float2(ai0 * rn0, ai1 * rn1);
    op[(C_OUT >> 1) * 2 + oh]    = make_float2(aj0 * rn0, aj1 * rn1);
    op[(C_OUT >> 1) * 3 + oh]    = make_float2(ak0 * rn0, ak1 * rn1);
}

extern "C" void kernel_launch(void* const* d_in, const int* in_sizes, int n_in,
                              void* d_out, int out_size) {
    const float* x      = (const float*)d_in[0];
    const float* weight = (const float*)d_in[1];
    const float* bias   = (const float*)d_in[2];
    float* out = (float*)d_out;
    (void)in_sizes; (void)n_in; (void)out_size;

    dim3 grid(NPAIR / PAIRS_PER_BLOCK, 2);   // 512 x 2 = 1024 blocks
    qpu_kernel<<<grid, THREADS>>>(x, weight, bias, out);
}

// round 13
// speedup vs baseline: 1.2833x; 1.1030x over previous
#include <cuda_runtime.h>
#include <math.h>

// Problem constants (fixed by setup_inputs)
#define C_IN   64
#define C_OUT  128
#define NPAIR  2048            // B*T = 16*128

#define THREADS 128            // 4 pairs x 32 o-pairs (2 o per thread)
#define PAIRS_PER_BLOCK 4
#define OH_PER_BLOCK 32        // o-pairs per block -> 64 o per block
#define WS2 33                 // padded float2 stride (conflict-free)

__device__ __forceinline__ float fsin_ap(float a) {
    float r; asm("sin.approx.f32 %0, %1;" : "=f"(r) : "f"(a)); return r;
}
__device__ __forceinline__ float frsq_ap(float a) {
    float r; asm("rsqrt.approx.f32 %0, %1;" : "=f"(r) : "f"(a)); return r;
}

__global__ __launch_bounds__(THREADS, 8)
void qpu_kernel(const float* __restrict__ x,      // (NPAIR, 4*C_IN) [r|i|j|k]
                const float* __restrict__ weight, // (C_OUT, C_IN)
                const float* __restrict__ bias,   // (C_OUT)
                float* __restrict__ out)          // (NPAIR, 4*C_OUT)
{
    __shared__ float2 w2_s[C_IN * WS2];             // [c*33 + oh] = {w[2oh], w[2oh+1]} transposed
    __shared__ float4 pc[PAIRS_PER_BLOCK][C_IN];    // {theta0, i*rn, j*rn, k*rn}

    const int tid   = threadIdx.x;
    const int p0    = blockIdx.x * PAIRS_PER_BLOCK;
    const int obase = blockIdx.y * (2 * OH_PER_BLOCK);   // 0 or 64

    // ---- stage o-slice of weight, transposed+paired: float4 loads, scalar scatter ----
    // Each iteration: thread loads weight[o, 4c..4c+3] as float4 (fully coalesced),
    // scatters the 4 scalars into w2_s[(4c..4c+3)*33 + o/2].{x|y}.
    #pragma unroll
    for (int q = 0; q < 8; ++q) {
        int item = q * THREADS + tid;          // 0..1023 over (64 o) x (16 c-quads)
        int ol   = item >> 4;                  // local o 0..63
        int cq   = item & 15;                  // c-quad 0..15
        float4 w4 = *(const float4*)(weight + (obase + ol) * C_IN + cq * 4);
        int oh = ol >> 1;
        float* dst0 = ((float*)&w2_s[(cq * 4 + 0) * WS2 + oh]) + (ol & 1);
        float* dst1 = ((float*)&w2_s[(cq * 4 + 1) * WS2 + oh]) + (ol & 1);
        float* dst2 = ((float*)&w2_s[(cq * 4 + 2) * WS2 + oh]) + (ol & 1);
        float* dst3 = ((float*)&w2_s[(cq * 4 + 3) * WS2 + oh]) + (ol & 1);
        *dst0 = w4.x; *dst1 = w4.y; *dst2 = w4.z; *dst3 = w4.w;
    }

    // ---- per-(pair,c) preprocessing: theta0 = acos(clip(r)), unit axis ----
    #pragma unroll
    for (int idx = tid; idx < PAIRS_PER_BLOCK * C_IN; idx += THREADS) {
        int pp = idx >> 6;
        int c  = idx & 63;
        const float* xr = x + (size_t)(p0 + pp) * (4 * C_IN);
        float r = xr[c];
        float i = xr[C_IN + c];
        float j = xr[2 * C_IN + c];
        float k = xr[3 * C_IN + c];
        float rn = rsqrtf(fmaf(i, i, fmaf(j, j, fmaf(k, k, 1e-12f))));
        const float CLAMP = 1.0f - 1e-6f;
        float rc = fminf(fmaxf(r, -CLAMP), CLAMP);
        float t0 = acosf(rc);
        pc[pp][c] = make_float4(t0, i * rn, j * rn, k * rn);
    }
    __syncthreads();

    // ---- main loop: one thread = (one pair, two adjacent o) ----
    const int pp = tid >> 5;          // pair within block (0..3)
    const int oh = tid & 31;          // local o-pair
    const float2 b2 = ((const float2*)bias)[(obase >> 1) + oh];

    const float4* pcb = &pc[pp][0];
    const float2* wb  = &w2_s[oh];

    // tan-normalized accumulators; implicit prod(cos) folds into final normalize
    float ar0 = 1.0f, ai0 = 0.0f, aj0 = 0.0f, ak0 = 0.0f;
    float ar1 = 1.0f, ai1 = 0.0f, aj1 = 0.0f, ak1 = 0.0f;

    #pragma unroll 16
    for (int c = 0; c < C_IN; ++c) {
        float4 p  = pcb[c];                    // LDS.128 broadcast
        float2 w2 = wb[c * WS2];               // LDS.64 conflict-free

        // --- interleaved: both MUFU chains launched before the Hamiltons ---
        float th0 = fmaf(w2.x, p.x, b2.x);     // |th| <= 0.733 < pi/2
        float th1 = fmaf(w2.y, p.x, b2.y);
        float s0  = fsin_ap(th0);              // MUFU.SIN
        float s1  = fsin_ap(th1);
        float o0  = fmaf(-s0, s0, 1.0f);
        float o1  = fmaf(-s1, s1, 1.0f);
        float t0  = s0 * frsq_ap(o0);          // tan = s * rsqrt(1-s^2)
        float t1  = s1 * frsq_ap(o1);

        float qi0 = p.y * t0, qj0 = p.z * t0, qk0 = p.w * t0;
        float qi1 = p.y * t1, qj1 = p.z * t1, qk1 = p.w * t1;

        // chain 0: acc = acc (x) (1, q)  -- 12 FMA
        float nr0 = ar0; nr0 = fmaf(-ai0, qi0, nr0); nr0 = fmaf(-aj0, qj0, nr0); nr0 = fmaf(-ak0, qk0, nr0);
        float ni0 = ai0; ni0 = fmaf( ar0, qi0, ni0); ni0 = fmaf( aj0, qk0, ni0); ni0 = fmaf(-ak0, qj0, ni0);
        float nj0 = aj0; nj0 = fmaf( ar0, qj0, nj0); nj0 = fmaf(-ai0, qk0, nj0); nj0 = fmaf( ak0, qi0, nj0);
        float nk0 = ak0; nk0 = fmaf( ar0, qk0, nk0); nk0 = fmaf( ai0, qj0, nk0); nk0 = fmaf(-aj0, qi0, nk0);
        ar0 = nr0; ai0 = ni0; aj0 = nj0; ak0 = nk0;

        // chain 1 (independent)
        float nr1 = ar1; nr1 = fmaf(-ai1, qi1, nr1); nr1 = fmaf(-aj1, qj1, nr1); nr1 = fmaf(-ak1, qk1, nr1);
        float ni1 = ai1; ni1 = fmaf( ar1, qi1, ni1); ni1 = fmaf( aj1, qk1, ni1); ni1 = fmaf(-ak1, qj1, ni1);
        float nj1 = aj1; nj1 = fmaf( ar1, qj1, nj1); nj1 = fmaf(-ai1, qk1, nj1); nj1 = fmaf( ak1, qi1, nj1);
        float nk1 = ak1; nk1 = fmaf( ar1, qk1, nk1); nk1 = fmaf( ai1, qj1, nk1); nk1 = fmaf(-aj1, qi1, nk1);
        ar1 = nr1; ai1 = ni1; aj1 = nj1; ak1 = nk1;
    }

    // ---- normalize + coalesced float2 writes ----
    float rn0 = rsqrtf(fmaf(ar0, ar0, fmaf(ai0, ai0, fmaf(aj0, aj0, fmaf(ak0, ak0, 1e-12f)))));
    float rn1 = rsqrtf(fmaf(ar1, ar1, fmaf(ai1, ai1, fmaf(aj1, aj1, fmaf(ak1, ak1, 1e-12f)))));

    float2* op = (float2*)(out + (size_t)(p0 + pp) * (4 * C_OUT) + obase);
    op[oh]                       = make_float2(ar0 * rn0, ar1 * rn1);
    op[(C_OUT >> 1) * 1 + oh]    = make_float2(ai0 * rn0, ai1 * rn1);
    op[(C_OUT >> 1) * 2 + oh]    = make_float2(aj0 * rn0, aj1 * rn1);
    op[(C_OUT >> 1) * 3 + oh]    = make_float2(ak0 * rn0, ak1 * rn1);
}

extern "C" void kernel_launch(void* const* d_in, const int* in_sizes, int n_in,
                              void* d_out, int out_size) {
    const float* x      = (const float*)d_in[0];
    const float* weight = (const float*)d_in[1];
    const float* bias   = (const float*)d_in[2];
    float* out = (float*)d_out;
    (void)in_sizes; (void)n_in; (void)out_size;

    dim3 grid(NPAIR / PAIRS_PER_BLOCK, 2);   // 512 x 2 = 1024 blocks
    qpu_kernel<<<grid, THREADS>>>(x, weight, bias, out);
}